// round 13
// baseline (speedup 1.0000x reference)
#include <cuda_runtime.h>
#include <math.h>

#define Bb 64
#define Pp 8
#define Nn 4096
#define Dd 256
#define Mm 4096
#define BPc 512
#define GRPB 16           // batches per L2-resident group (64 MB feats)
#define EPSC 1e-8f
#define FULLW 0xFFFFFFFFu

// ---- static device scratch ----
__device__ float    g_sim[(size_t)Bb * Nn * Pp];   // raw sim, exp'd in place
__device__ float    g_rnorm[Bb * Nn];
__device__ float    g_pn[BPc * Dd];
__device__ unsigned g_max[BPc];
__device__ float    g_zpart[Bb * 16 * Pp];
__device__ int      g_cnt[2][BPc];
__device__ int      g_idx[Bb * Nn];
__device__ float    g_msum[Bb * 16 * Pp];
__device__ float    g_ppart[(size_t)Bb * 16 * Pp * Dd];

typedef unsigned long long u64;

__device__ __forceinline__ void fma2(u64& d, u64 a, u64 b) {
    asm("fma.rn.f32x2 %0, %1, %2, %0;" : "+l"(d) : "l"(a), "l"(b));
}
__device__ __forceinline__ void add2(u64& d, u64 a) {
    asm("add.rn.f32x2 %0, %0, %1;" : "+l"(d) : "l"(a));
}
__device__ __forceinline__ float2 upk(u64 v) {
    float2 r; asm("mov.b64 {%0,%1}, %2;" : "=f"(r.x), "=f"(r.y) : "l"(v)); return r;
}
__device__ __forceinline__ u64 pk(float x, float y) {
    u64 r; asm("mov.b64 %0, {%1,%2};" : "=l"(r) : "f"(x), "f"(y)); return r;
}

// ---- cp.async helpers ----
__device__ __forceinline__ void cpa16(unsigned dst, const void* src) {
    asm volatile("cp.async.cg.shared.global [%0], [%1], 16;" :: "r"(dst), "l"(src));
}
__device__ __forceinline__ void cpcommit() { asm volatile("cp.async.commit_group;"); }
__device__ __forceinline__ void cpwait2() { asm volatile("cp.async.wait_group 2;"); }

__device__ __forceinline__ unsigned f2ord(float f) {
    unsigned u = __float_as_uint(f);
    return (u & 0x80000000u) ? ~u : (u | 0x80000000u);
}
__device__ __forceinline__ float ord2f(unsigned u) {
    return (u & 0x80000000u) ? __uint_as_float(u & 0x7FFFFFFFu) : __uint_as_float(~u);
}

template<bool MX>
__device__ __forceinline__ void red8(float v[8]) {
#pragma unroll
    for (int off = 16; off; off >>= 1) {
#pragma unroll
        for (int p = 0; p < 8; p++) {
            float o = __shfl_xor_sync(FULLW, v[p], off);
            v[p] = MX ? fmaxf(v[p], o) : (v[p] + o);
        }
    }
}

__device__ __forceinline__ float block_sum256(float v, float* r8) {
#pragma unroll
    for (int off = 16; off; off >>= 1) v += __shfl_xor_sync(FULLW, v, off);
    if ((threadIdx.x & 31) == 0) r8[threadIdx.x >> 5] = v;
    __syncthreads();
    if (threadIdx.x == 0) {
        float t = 0.f;
#pragma unroll
        for (int w = 0; w < 8; w++) t += r8[w];
        r8[0] = t;
    }
    __syncthreads();
    return r8[0];
}

// ---- init ----
__global__ void __launch_bounds__(256) k_norm0(const float* __restrict__ pin) {
    __shared__ float r8[8];
    int bp = blockIdx.x, tid = threadIdx.x;
    float v = pin[(size_t)bp * Dd + tid];
    float ss = block_sum256(v * v, r8);
    g_pn[(size_t)bp * Dd + tid] = v / fmaxf(sqrtf(ss), EPSC);
    if (tid == 0) { g_max[bp] = 0u; g_cnt[0][bp] = 0; g_cnt[1][bp] = 0; }
}

// ---- sim pass: 4-stage cp.async ring (R10 proven) ----
#define SIMSMEM (8192 + 4 * 16384 + 256)

template<bool FIRST, bool DENS>
__global__ void __launch_bounds__(256) k_sim(const float* __restrict__ feats, int bofs) {
    extern __shared__ char smraw[];
    float4* pn_s = (float4*)smraw;
    float*  fs   = (float*)(smraw + 8192);
    float*  red  = (float*)(smraw + 8192 + 4 * 16384);

    int b = bofs + (blockIdx.x >> 4), c = blockIdx.x & 15;
    int tid = threadIdx.x, lane = tid & 31, wid = tid >> 5;

    const float4* psrc = (const float4*)g_pn + (size_t)b * 512;
    for (int i = tid; i < 512; i += 256) pn_s[i] = psrc[i];

    const float* fbase = feats + ((size_t)b * Nn + c * 256) * Dd;
    int r0 = tid >> 2, j = tid & 3;
    unsigned fsb = (unsigned)__cvta_generic_to_shared(fs);

#pragma unroll
    for (int s = 0; s < 3; s++) {
#pragma unroll
        for (int k = 0; k < 4; k++) {
            int row = r0 + 64 * k;
            int jc = j ^ (row & 3);
            cpa16(fsb + (s << 14) + row * 64 + jc * 16,
                  fbase + (size_t)row * Dd + s * 16 + j * 4);
        }
        cpcommit();
    }

    u64 acc[8];
#pragma unroll
    for (int p = 0; p < 8; p++) acc[p] = 0ull;
    u64 sq = 0ull;
    int sw = tid & 3;

    for (int s = 0; s < 16; s++) {
        cpwait2();
        __syncthreads();
        const float* fb = fs + ((s & 3) << 12);
#pragma unroll
        for (int jj = 0; jj < 4; jj++) {
            ulonglong2 f2 = *(const ulonglong2*)&fb[tid * 16 + ((jj ^ sw) << 2)];
            if (FIRST) { fma2(sq, f2.x, f2.x); fma2(sq, f2.y, f2.y); }
#pragma unroll
            for (int p = 0; p < 8; p++) {
                ulonglong2 q2 = *(const ulonglong2*)(pn_s + p * 64 + s * 4 + jj);
                fma2(acc[p], f2.x, q2.x);
                fma2(acc[p], f2.y, q2.y);
            }
        }
        int ss = s + 3;
        if (ss < 16) {
#pragma unroll
            for (int k = 0; k < 4; k++) {
                int row = r0 + 64 * k;
                int jc = j ^ (row & 3);
                cpa16(fsb + ((ss & 3) << 14) + row * 64 + jc * 16,
                      fbase + (size_t)row * Dd + ss * 16 + j * 4);
            }
        }
        cpcommit();
    }

    int n = c * 256 + tid;
    float rn;
    if (FIRST) {
        float2 sv = upk(sq);
        rn = 1.f / fmaxf(sqrtf(sv.x + sv.y), EPSC);
        g_rnorm[b * Nn + n] = rn;
    } else rn = g_rnorm[b * Nn + n];

    float sim[8];
#pragma unroll
    for (int p = 0; p < 8; p++) {
        float2 a = upk(acc[p]);
        sim[p] = (a.x + a.y) * rn;
    }
    float4* o = (float4*)(g_sim + ((size_t)b * Nn + n) * 8);
    o[0] = make_float4(sim[0], sim[1], sim[2], sim[3]);
    o[1] = make_float4(sim[4], sim[5], sim[6], sim[7]);

    float mv[8];
#pragma unroll
    for (int p = 0; p < 8; p++) mv[p] = sim[p];
    red8<true>(mv);
    __syncthreads();
    if (lane < 8) red[wid * 8 + lane] = mv[lane];
    __syncthreads();
    if (tid < 8) {
        float m = red[tid];
#pragma unroll
        for (int w = 1; w < 8; w++) m = fmaxf(m, red[w * 8 + tid]);
        atomicMax(&g_max[b * 8 + tid], f2ord(m));
    }

    if (DENS) {
        int a = g_idx[b * Nn + n];
        float dv[8];
#pragma unroll
        for (int p = 0; p < 8; p++) dv[p] = (p == a) ? sim[p] : 0.f;
        red8<false>(dv);
        __syncthreads();
        if (lane < 8) red[wid * 8 + lane] = dv[lane];
        __syncthreads();
        if (tid < 8) {
            float s2 = red[tid];
#pragma unroll
            for (int w = 1; w < 8; w++) s2 += red[w * 8 + tid];
            g_msum[((size_t)b * 16 + c) * 8 + tid] = s2;
        }
    }
}

// ---- stats: tau; exp in place; Z partials (one 256-row chunk per block) ----
template<bool HAS_TAU>
__global__ void __launch_bounds__(256) k_stats(int par, int bofs) {
    int b = bofs + (blockIdx.x >> 4), c = blockIdx.x & 15;
    int tid = threadIdx.x, lane = tid & 31, wid = tid >> 5;
    __shared__ float mxs[8], iss[8], red[64];
    if (tid < 8) {
        mxs[tid] = ord2f(g_max[b * 8 + tid]);
        float is;
        if (HAS_TAU) {
            float s = 0.f;
#pragma unroll
            for (int cc = 0; cc < 16; cc++) s += g_msum[((size_t)b * 16 + cc) * 8 + tid];
            int cnt = g_cnt[par][b * 8 + tid];
            float mean = s / (float)(cnt >= 1 ? cnt : 1);
            float dens = (cnt >= 1) ? (1.f - mean) : 1.f;
            is = 1.f / (0.1f * fmaxf(dens, 1e-10f));
        } else {
            is = 100.f;
        }
        iss[tid] = is;
    }
    __syncthreads();
    float z[8];
    {
        int n = c * 256 + tid;
        float4* p4 = (float4*)(g_sim + ((size_t)b * Nn + n) * 8);
        float4 a = p4[0], cc = p4[1];
        a.x  = expf((a.x  - mxs[0]) * iss[0]); z[0] = a.x;
        a.y  = expf((a.y  - mxs[1]) * iss[1]); z[1] = a.y;
        a.z  = expf((a.z  - mxs[2]) * iss[2]); z[2] = a.z;
        a.w  = expf((a.w  - mxs[3]) * iss[3]); z[3] = a.w;
        cc.x = expf((cc.x - mxs[4]) * iss[4]); z[4] = cc.x;
        cc.y = expf((cc.y - mxs[5]) * iss[5]); z[5] = cc.y;
        cc.z = expf((cc.z - mxs[6]) * iss[6]); z[6] = cc.z;
        cc.w = expf((cc.w - mxs[7]) * iss[7]); z[7] = cc.w;
        p4[0] = a; p4[1] = cc;
    }
    red8<false>(z);
    if (lane < 8) red[wid * 8 + lane] = z[lane];
    __syncthreads();
    if (tid < 8) {
        float s = red[tid];
#pragma unroll
        for (int w = 1; w < 8; w++) s += red[w * 8 + tid];
        g_zpart[((size_t)b * 16 + c) * 8 + tid] = s;
    }
}

// ---- update v4 (fp32, R10 proven): 2 cols/thread, batched LDG.64 ----
__global__ void __launch_bounds__(256) k_update(const float* __restrict__ feats,
                                                int parw, int bofs) {
    int b = bofs + (blockIdx.x >> 4), ch = blockIdx.x & 15;
    int tid = threadIdx.x, lane = tid & 31;
    __shared__ float ws[256];
    __shared__ int   bis[256];
    __shared__ u64   part[8][128];
    __shared__ float izs[8];

    if (tid < 8) {
        float z = 0.f;
#pragma unroll
        for (int q = 0; q < 16; q++) z += g_zpart[((size_t)b * 16 + q) * 8 + tid];
        izs[tid] = 1.f / z;
    }
    __syncthreads();

    int base = ch * 256;
    {
        const float4* sp = (const float4*)(g_sim + ((size_t)b * Nn + base + tid) * 8);
        float4 e0 = sp[0], e1 = sp[1];
        float w[8] = { e0.x * izs[0], e0.y * izs[1], e0.z * izs[2], e0.w * izs[3],
                       e1.x * izs[4], e1.y * izs[5], e1.z * izs[6], e1.w * izs[7] };
        int bi = 0; float bw = w[0];
#pragma unroll
        for (int p = 1; p < 8; p++) if (w[p] > bw) { bw = w[p]; bi = p; }
        g_idx[b * Nn + base + tid] = bi;
        ws[tid] = bw;
        bis[tid] = bi;
        int mycnt = 0;
#pragma unroll
        for (int p = 0; p < 8; p++) {
            unsigned mk = __ballot_sync(FULLW, bi == p);
            if (lane == p) mycnt += __popc(mk);
        }
        if (lane < 8) atomicAdd(&g_cnt[parw][b * 8 + lane], mycnt);
    }
    __syncthreads();

    int g2 = tid >> 7;
    int t = tid & 127;
    const float* fb = feats + ((size_t)b * Nn + base + g2 * 128) * Dd;

    u64 acc[8];
#pragma unroll
    for (int p = 0; p < 8; p++) acc[p] = 0ull;

    for (int r0 = 0; r0 < 128; r0 += 8) {
        u64 f[8];
#pragma unroll
        for (int k = 0; k < 8; k++)
            f[k] = __ldg((const u64*)(fb + (size_t)(r0 + k) * Dd + 2 * t));
#pragma unroll
        for (int k = 0; k < 8; k++) {
            int row = (g2 << 7) + r0 + k;
            float wv = ws[row];
            int bi = bis[row];           // uniform across the warp
            u64 wp = pk(wv, wv);
            if (bi < 4) {
                if (bi < 2) { if (bi == 0) fma2(acc[0], wp, f[k]); else fma2(acc[1], wp, f[k]); }
                else        { if (bi == 2) fma2(acc[2], wp, f[k]); else fma2(acc[3], wp, f[k]); }
            } else {
                if (bi < 6) { if (bi == 4) fma2(acc[4], wp, f[k]); else fma2(acc[5], wp, f[k]); }
                else        { if (bi == 6) fma2(acc[6], wp, f[k]); else fma2(acc[7], wp, f[k]); }
            }
        }
    }

    if (g2 == 1) {
#pragma unroll
        for (int p = 0; p < 8; p++) part[p][t] = acc[p];
    }
    __syncthreads();
    if (g2 == 0) {
        float* op = g_ppart + ((size_t)(b * 16 + ch)) * 2048;
#pragma unroll
        for (int p = 0; p < 8; p++) {
            add2(acc[p], part[p][t]);
            float2 a = upk(acc[p]);
            *(float2*)(op + p * 256 + 2 * t) = a;
        }
    }
}

// ---- reduce 16 partials -> prototypes; normalize; reset state ----
__global__ void __launch_bounds__(256) k_reduce(float* __restrict__ outp, int parzero,
                                                int bofs) {
    __shared__ float r8[8];
    int bp = bofs * 8 + blockIdx.x;
    int b = bp >> 3, p = bp & 7;
    int tid = threadIdx.x;
    float v = 0.f;
#pragma unroll
    for (int c = 0; c < 16; c++)
        v += g_ppart[((size_t)(b * 16 + c)) * 2048 + p * 256 + tid];
    float ss = block_sum256(v * v, r8);
    float rn = 1.f / fmaxf(sqrtf(ss), EPSC);
    outp[(size_t)bp * Dd + tid] = v;
    g_pn[(size_t)bp * Dd + tid] = v * rn;
    if (tid == 0) { g_max[bp] = 0u; g_cnt[parzero][bp] = 0; }
}

// ---- final sim_map: cp.async ring, inline rnorm ----
__global__ void __launch_bounds__(256) k_simmap(const float* __restrict__ forg,
                                                float* __restrict__ out) {
    extern __shared__ char smraw[];
    float4* pn_s = (float4*)smraw;
    float*  fs   = (float*)(smraw + 8192);

    int b = blockIdx.x >> 4, c = blockIdx.x & 15;
    int tid = threadIdx.x;

    const float4* psrc = (const float4*)g_pn + (size_t)b * 512;
    for (int i = tid; i < 512; i += 256) pn_s[i] = psrc[i];

    const float* fbase = forg + (size_t)c * 256 * Dd;
    int r0 = tid >> 2, j = tid & 3;
    unsigned fsb = (unsigned)__cvta_generic_to_shared(fs);

#pragma unroll
    for (int s = 0; s < 3; s++) {
#pragma unroll
        for (int k = 0; k < 4; k++) {
            int row = r0 + 64 * k;
            int jc = j ^ (row & 3);
            cpa16(fsb + (s << 14) + row * 64 + jc * 16,
                  fbase + (size_t)row * Dd + s * 16 + j * 4);
        }
        cpcommit();
    }

    u64 acc[8];
#pragma unroll
    for (int p = 0; p < 8; p++) acc[p] = 0ull;
    u64 sq = 0ull;
    int sw = tid & 3;

    for (int s = 0; s < 16; s++) {
        cpwait2();
        __syncthreads();
        const float* fb = fs + ((s & 3) << 12);
#pragma unroll
        for (int jj = 0; jj < 4; jj++) {
            ulonglong2 f2 = *(const ulonglong2*)&fb[tid * 16 + ((jj ^ sw) << 2)];
            fma2(sq, f2.x, f2.x); fma2(sq, f2.y, f2.y);
#pragma unroll
            for (int p = 0; p < 8; p++) {
                ulonglong2 q2 = *(const ulonglong2*)(pn_s + p * 64 + s * 4 + jj);
                fma2(acc[p], f2.x, q2.x);
                fma2(acc[p], f2.y, q2.y);
            }
        }
        int ss = s + 3;
        if (ss < 16) {
#pragma unroll
            for (int k = 0; k < 4; k++) {
                int row = r0 + 64 * k;
                int jc = j ^ (row & 3);
                cpa16(fsb + ((ss & 3) << 14) + row * 64 + jc * 16,
                      fbase + (size_t)row * Dd + ss * 16 + j * 4);
            }
        }
        cpcommit();
    }

    int m = c * 256 + tid;
    float2 sv = upk(sq);
    float rn = 1.f / fmaxf(sqrtf(sv.x + sv.y), EPSC);
#pragma unroll
    for (int p = 0; p < 8; p++) {
        float2 a = upk(acc[p]);
        out[((size_t)b * Pp + p) * Mm + m] = (a.x + a.y) * rn;
    }
}

extern "C" void kernel_launch(void* const* d_in, const int* in_sizes, int n_in,
                              void* d_out, int out_size) {
    const float* protos = (const float*)d_in[0];
    const float* feats  = (const float*)d_in[1];
    const float* forg   = (const float*)d_in[2];
    float* out = (float*)d_out;

    cudaFuncSetAttribute(k_sim<true, false>,
                         cudaFuncAttributeMaxDynamicSharedMemorySize, SIMSMEM);
    cudaFuncSetAttribute(k_sim<false, true>,
                         cudaFuncAttributeMaxDynamicSharedMemorySize, SIMSMEM);
    cudaFuncSetAttribute(k_simmap,
                         cudaFuncAttributeMaxDynamicSharedMemorySize, SIMSMEM);

    k_norm0<<<BPc, 256>>>(protos);

    // group-wise: all 5 iterations for one 64MB feats slice (stays L2-resident)
    for (int g = 0; g < Bb / GRPB; g++) {
        int bofs = g * GRPB;
        k_sim<true, false><<<GRPB * 16, 256, SIMSMEM>>>(feats, bofs);
        k_stats<false><<<GRPB * 16, 256>>>(0, bofs);
        k_update<<<GRPB * 16, 256>>>(feats, 0, bofs);
        k_reduce<<<GRPB * 8, 256>>>(out, 1, bofs);
        for (int t = 1; t < 5; t++) {
            k_sim<false, true><<<GRPB * 16, 256, SIMSMEM>>>(feats, bofs);
            k_stats<true><<<GRPB * 16, 256>>>((t - 1) & 1, bofs);
            k_update<<<GRPB * 16, 256>>>(feats, t & 1, bofs);
            k_reduce<<<GRPB * 8, 256>>>(out, (t + 1) & 1, bofs);
        }
    }

    k_simmap<<<Bb * 16, 256, SIMSMEM>>>(forg, out + (size_t)BPc * Dd);
}

// round 14
// speedup vs baseline: 1.1371x; 1.1371x over previous
#include <cuda_runtime.h>
#include <math.h>

#define Bb 64
#define Pp 8
#define Nn 4096
#define Dd 256
#define Mm 4096
#define BPc 512
#define EPSC 1e-8f
#define FULLW 0xFFFFFFFFu

// ---- static device scratch ----
__device__ float    g_sim[(size_t)Bb * Nn * Pp];   // raw sim, exp'd in place
__device__ float    g_rnorm[Bb * Nn];
__device__ float    g_pn[BPc * Dd];
__device__ unsigned g_max[BPc];
__device__ float    g_zpart[Bb * 16 * Pp];
__device__ int      g_cnt[2][BPc];
__device__ int      g_idx[Bb * Nn];
__device__ float    g_msum[Bb * 16 * Pp];
__device__ float    g_ppart[(size_t)Bb * 16 * Pp * Dd];

typedef unsigned long long u64;

__device__ __forceinline__ void fma2(u64& d, u64 a, u64 b) {
    asm("fma.rn.f32x2 %0, %1, %2, %0;" : "+l"(d) : "l"(a), "l"(b));
}
__device__ __forceinline__ void add2(u64& d, u64 a) {
    asm("add.rn.f32x2 %0, %0, %1;" : "+l"(d) : "l"(a));
}
__device__ __forceinline__ float2 upk(u64 v) {
    float2 r; asm("mov.b64 {%0,%1}, %2;" : "=f"(r.x), "=f"(r.y) : "l"(v)); return r;
}
__device__ __forceinline__ u64 pk(float x, float y) {
    u64 r; asm("mov.b64 %0, {%1,%2};" : "=l"(r) : "f"(x), "f"(y)); return r;
}

// ---- cp.async helpers ----
__device__ __forceinline__ void cpa16(unsigned dst, const void* src) {
    asm volatile("cp.async.cg.shared.global [%0], [%1], 16;" :: "r"(dst), "l"(src));
}
__device__ __forceinline__ void cpcommit() { asm volatile("cp.async.commit_group;"); }
__device__ __forceinline__ void cpwait2() { asm volatile("cp.async.wait_group 2;"); }

__device__ __forceinline__ unsigned f2ord(float f) {
    unsigned u = __float_as_uint(f);
    return (u & 0x80000000u) ? ~u : (u | 0x80000000u);
}
__device__ __forceinline__ float ord2f(unsigned u) {
    return (u & 0x80000000u) ? __uint_as_float(u & 0x7FFFFFFFu) : __uint_as_float(~u);
}

template<bool MX>
__device__ __forceinline__ void red8(float v[8]) {
#pragma unroll
    for (int off = 16; off; off >>= 1) {
#pragma unroll
        for (int p = 0; p < 8; p++) {
            float o = __shfl_xor_sync(FULLW, v[p], off);
            v[p] = MX ? fmaxf(v[p], o) : (v[p] + o);
        }
    }
}

__device__ __forceinline__ float block_sum256(float v, float* r8) {
#pragma unroll
    for (int off = 16; off; off >>= 1) v += __shfl_xor_sync(FULLW, v, off);
    if ((threadIdx.x & 31) == 0) r8[threadIdx.x >> 5] = v;
    __syncthreads();
    if (threadIdx.x == 0) {
        float t = 0.f;
#pragma unroll
        for (int w = 0; w < 8; w++) t += r8[w];
        r8[0] = t;
    }
    __syncthreads();
    return r8[0];
}

// ---- init ----
__global__ void __launch_bounds__(256) k_norm0(const float* __restrict__ pin) {
    __shared__ float r8[8];
    int bp = blockIdx.x, tid = threadIdx.x;
    float v = pin[(size_t)bp * Dd + tid];
    float ss = block_sum256(v * v, r8);
    g_pn[(size_t)bp * Dd + tid] = v / fmaxf(sqrtf(ss), EPSC);
    if (tid == 0) { g_max[bp] = 0u; g_cnt[0][bp] = 0; g_cnt[1][bp] = 0; }
}

// ---- sim pass: continuous 32-stage cp.async ring over 2 tiles per CTA ----
#define SIMSMEM (8192 + 4 * 16384 + 256)

template<bool FIRST, bool DENS>
__global__ void __launch_bounds__(256) k_sim(const float* __restrict__ feats) {
    extern __shared__ char smraw[];
    float4* pn_s = (float4*)smraw;
    float*  fs   = (float*)(smraw + 8192);
    float*  red  = (float*)(smraw + 8192 + 4 * 16384);

    int b = blockIdx.x >> 3, c8 = blockIdx.x & 7;
    int tid = threadIdx.x, lane = tid & 31, wid = tid >> 5;

    const float4* psrc = (const float4*)g_pn + (size_t)b * 512;
    for (int i = tid; i < 512; i += 256) pn_s[i] = psrc[i];

    const float* fbase = feats + ((size_t)b * Nn + c8 * 512) * Dd;   // 512 rows
    int r0 = tid >> 2, j = tid & 3;
    int jc = j ^ (r0 & 3);          // localrow = r0 + 64k keeps (row&3) == (r0&3)
    unsigned fsb = (unsigned)__cvta_generic_to_shared(fs);

    // stage s (0..31): rows (s>>4)*256 .. +255, cols (s&15)*16 .. +15
#pragma unroll
    for (int s = 0; s < 3; s++) {
#pragma unroll
        for (int k = 0; k < 4; k++) {
            int lrow = r0 + 64 * k;
            cpa16(fsb + ((s & 3) << 14) + lrow * 64 + (j ^ (lrow & 3)) * 16,
                  fbase + (size_t)((s >> 4) * 256 + lrow) * Dd + (s & 15) * 16 + j * 4);
        }
        cpcommit();
    }
    (void)jc;

    int sw = tid & 3;

#pragma unroll 1
    for (int t = 0; t < 2; t++) {
        u64 acc[8];
#pragma unroll
        for (int p = 0; p < 8; p++) acc[p] = 0ull;
        u64 sq = 0ull;

#pragma unroll 1
        for (int s2 = 0; s2 < 16; s2++) {
            int s = t * 16 + s2;
            cpwait2();
            __syncthreads();
            const float* fb = fs + ((s & 3) << 12);
#pragma unroll
            for (int jj = 0; jj < 4; jj++) {
                ulonglong2 f2 = *(const ulonglong2*)&fb[tid * 16 + ((jj ^ sw) << 2)];
                if (FIRST) { fma2(sq, f2.x, f2.x); fma2(sq, f2.y, f2.y); }
#pragma unroll
                for (int p = 0; p < 8; p++) {
                    ulonglong2 q2 = *(const ulonglong2*)(pn_s + p * 64 + s2 * 4 + jj);
                    fma2(acc[p], f2.x, q2.x);
                    fma2(acc[p], f2.y, q2.y);
                }
            }
            int ss = s + 3;
            if (ss < 32) {
#pragma unroll
                for (int k = 0; k < 4; k++) {
                    int lrow = r0 + 64 * k;
                    cpa16(fsb + ((ss & 3) << 14) + lrow * 64 + (j ^ (lrow & 3)) * 16,
                          fbase + (size_t)((ss >> 4) * 256 + lrow) * Dd + (ss & 15) * 16 + j * 4);
                }
            }
            cpcommit();
        }

        // ---- epilogue for tile t ----
        int n = c8 * 512 + t * 256 + tid;
        float rn;
        if (FIRST) {
            float2 sv = upk(sq);
            rn = 1.f / fmaxf(sqrtf(sv.x + sv.y), EPSC);
            g_rnorm[b * Nn + n] = rn;
        } else rn = g_rnorm[b * Nn + n];

        float sim[8];
#pragma unroll
        for (int p = 0; p < 8; p++) {
            float2 a = upk(acc[p]);
            sim[p] = (a.x + a.y) * rn;
        }
        float4* o = (float4*)(g_sim + ((size_t)b * Nn + n) * 8);
        o[0] = make_float4(sim[0], sim[1], sim[2], sim[3]);
        o[1] = make_float4(sim[4], sim[5], sim[6], sim[7]);

        float mv[8];
#pragma unroll
        for (int p = 0; p < 8; p++) mv[p] = sim[p];
        red8<true>(mv);
        __syncthreads();
        if (lane < 8) red[wid * 8 + lane] = mv[lane];
        __syncthreads();
        if (tid < 8) {
            float m = red[tid];
#pragma unroll
            for (int w = 1; w < 8; w++) m = fmaxf(m, red[w * 8 + tid]);
            atomicMax(&g_max[b * 8 + tid], f2ord(m));
        }

        if (DENS) {
            int a = g_idx[b * Nn + n];
            float dv[8];
#pragma unroll
            for (int p = 0; p < 8; p++) dv[p] = (p == a) ? sim[p] : 0.f;
            red8<false>(dv);
            __syncthreads();
            if (lane < 8) red[wid * 8 + lane] = dv[lane];
            __syncthreads();
            if (tid < 8) {
                float s2v = red[tid];
#pragma unroll
                for (int w = 1; w < 8; w++) s2v += red[w * 8 + tid];
                g_msum[((size_t)b * 16 + c8 * 2 + t) * 8 + tid] = s2v;
            }
        }
        __syncthreads();
    }
}

// ---- stats: tau; exp in place; Z partials (one 256-row chunk per block) ----
template<bool HAS_TAU>
__global__ void __launch_bounds__(256) k_stats(int par) {
    int b = blockIdx.x >> 4, c = blockIdx.x & 15;
    int tid = threadIdx.x, lane = tid & 31, wid = tid >> 5;
    __shared__ float mxs[8], iss[8], red[64];
    if (tid < 8) {
        mxs[tid] = ord2f(g_max[b * 8 + tid]);
        float is;
        if (HAS_TAU) {
            float s = 0.f;
#pragma unroll
            for (int cc = 0; cc < 16; cc++) s += g_msum[((size_t)b * 16 + cc) * 8 + tid];
            int cnt = g_cnt[par][b * 8 + tid];
            float mean = s / (float)(cnt >= 1 ? cnt : 1);
            float dens = (cnt >= 1) ? (1.f - mean) : 1.f;
            is = 1.f / (0.1f * fmaxf(dens, 1e-10f));
        } else {
            is = 100.f;
        }
        iss[tid] = is;
    }
    __syncthreads();
    float z[8];
    {
        int n = c * 256 + tid;
        float4* p4 = (float4*)(g_sim + ((size_t)b * Nn + n) * 8);
        float4 a = p4[0], cc = p4[1];
        a.x  = expf((a.x  - mxs[0]) * iss[0]); z[0] = a.x;
        a.y  = expf((a.y  - mxs[1]) * iss[1]); z[1] = a.y;
        a.z  = expf((a.z  - mxs[2]) * iss[2]); z[2] = a.z;
        a.w  = expf((a.w  - mxs[3]) * iss[3]); z[3] = a.w;
        cc.x = expf((cc.x - mxs[4]) * iss[4]); z[4] = cc.x;
        cc.y = expf((cc.y - mxs[5]) * iss[5]); z[5] = cc.y;
        cc.z = expf((cc.z - mxs[6]) * iss[6]); z[6] = cc.z;
        cc.w = expf((cc.w - mxs[7]) * iss[7]); z[7] = cc.w;
        p4[0] = a; p4[1] = cc;
    }
    red8<false>(z);
    if (lane < 8) red[wid * 8 + lane] = z[lane];
    __syncthreads();
    if (tid < 8) {
        float s = red[tid];
#pragma unroll
        for (int w = 1; w < 8; w++) s += red[w * 8 + tid];
        g_zpart[((size_t)b * 16 + c) * 8 + tid] = s;
    }
}

// ---- update v4: 2 chunks per CTA, 2 cols/thread, batched LDG.64 ----
__global__ void __launch_bounds__(256) k_update(const float* __restrict__ feats,
                                                int parw) {
    int b = blockIdx.x >> 3, ch0 = blockIdx.x & 7;
    int tid = threadIdx.x, lane = tid & 31;
    __shared__ float ws[256];
    __shared__ int   bis[256];
    __shared__ u64   part[8][128];
    __shared__ float izs[8];

    if (tid < 8) {
        float z = 0.f;
#pragma unroll
        for (int q = 0; q < 16; q++) z += g_zpart[((size_t)b * 16 + q) * 8 + tid];
        izs[tid] = 1.f / z;
    }
    __syncthreads();

#pragma unroll 1
    for (int i = 0; i < 2; i++) {
        int ch = ch0 * 2 + i;
        int base = ch * 256;
        // ---- phase 1: row tid -> weight + argmax ----
        {
            const float4* sp = (const float4*)(g_sim + ((size_t)b * Nn + base + tid) * 8);
            float4 e0 = sp[0], e1 = sp[1];
            float w[8] = { e0.x * izs[0], e0.y * izs[1], e0.z * izs[2], e0.w * izs[3],
                           e1.x * izs[4], e1.y * izs[5], e1.z * izs[6], e1.w * izs[7] };
            int bi = 0; float bw = w[0];
#pragma unroll
            for (int p = 1; p < 8; p++) if (w[p] > bw) { bw = w[p]; bi = p; }
            g_idx[b * Nn + base + tid] = bi;
            ws[tid] = bw;
            bis[tid] = bi;
            int mycnt = 0;
#pragma unroll
            for (int p = 0; p < 8; p++) {
                unsigned mk = __ballot_sync(FULLW, bi == p);
                if (lane == p) mycnt += __popc(mk);
            }
            if (lane < 8) atomicAdd(&g_cnt[parw][b * 8 + lane], mycnt);
        }
        __syncthreads();

        // ---- phase 2: group g2 streams 128 rows; thread owns cols 2t,2t+1 ----
        int g2 = tid >> 7;
        int t = tid & 127;
        const float* fb = feats + ((size_t)b * Nn + base + g2 * 128) * Dd;

        u64 acc[8];
#pragma unroll
        for (int p = 0; p < 8; p++) acc[p] = 0ull;

        for (int r0 = 0; r0 < 128; r0 += 8) {
            u64 f[8];
#pragma unroll
            for (int k = 0; k < 8; k++)
                f[k] = __ldg((const u64*)(fb + (size_t)(r0 + k) * Dd + 2 * t));
#pragma unroll
            for (int k = 0; k < 8; k++) {
                int row = (g2 << 7) + r0 + k;
                float wv = ws[row];
                int bi = bis[row];           // uniform across the warp
                u64 wp = pk(wv, wv);
                if (bi < 4) {
                    if (bi < 2) { if (bi == 0) fma2(acc[0], wp, f[k]); else fma2(acc[1], wp, f[k]); }
                    else        { if (bi == 2) fma2(acc[2], wp, f[k]); else fma2(acc[3], wp, f[k]); }
                } else {
                    if (bi < 6) { if (bi == 4) fma2(acc[4], wp, f[k]); else fma2(acc[5], wp, f[k]); }
                    else        { if (bi == 6) fma2(acc[6], wp, f[k]); else fma2(acc[7], wp, f[k]); }
                }
            }
        }

        if (g2 == 1) {
#pragma unroll
            for (int p = 0; p < 8; p++) part[p][t] = acc[p];
        }
        __syncthreads();
        if (g2 == 0) {
            float* op = g_ppart + ((size_t)(b * 16 + ch)) * 2048;
#pragma unroll
            for (int p = 0; p < 8; p++) {
                add2(acc[p], part[p][t]);
                float2 a = upk(acc[p]);
                *(float2*)(op + p * 256 + 2 * t) = a;
            }
        }
        __syncthreads();
    }
}

// ---- reduce 16 partials -> prototypes; normalize; reset state ----
__global__ void __launch_bounds__(256) k_reduce(float* __restrict__ outp, int parzero) {
    __shared__ float r8[8];
    int bp = blockIdx.x, b = bp >> 3, p = bp & 7;
    int tid = threadIdx.x;
    float v = 0.f;
#pragma unroll
    for (int c = 0; c < 16; c++)
        v += g_ppart[((size_t)(b * 16 + c)) * 2048 + p * 256 + tid];
    float ss = block_sum256(v * v, r8);
    float rn = 1.f / fmaxf(sqrtf(ss), EPSC);
    outp[(size_t)bp * Dd + tid] = v;
    g_pn[(size_t)bp * Dd + tid] = v * rn;
    if (tid == 0) { g_max[bp] = 0u; g_cnt[parzero][bp] = 0; }
}

// ---- final sim_map: continuous ring over 2 tiles, inline rnorm ----
__global__ void __launch_bounds__(256) k_simmap(const float* __restrict__ forg,
                                                float* __restrict__ out) {
    extern __shared__ char smraw[];
    float4* pn_s = (float4*)smraw;
    float*  fs   = (float*)(smraw + 8192);

    int b = blockIdx.x >> 3, c8 = blockIdx.x & 7;
    int tid = threadIdx.x;

    const float4* psrc = (const float4*)g_pn + (size_t)b * 512;
    for (int i = tid; i < 512; i += 256) pn_s[i] = psrc[i];

    const float* fbase = forg + (size_t)c8 * 512 * Dd;
    int r0 = tid >> 2, j = tid & 3;
    unsigned fsb = (unsigned)__cvta_generic_to_shared(fs);

#pragma unroll
    for (int s = 0; s < 3; s++) {
#pragma unroll
        for (int k = 0; k < 4; k++) {
            int lrow = r0 + 64 * k;
            cpa16(fsb + ((s & 3) << 14) + lrow * 64 + (j ^ (lrow & 3)) * 16,
                  fbase + (size_t)((s >> 4) * 256 + lrow) * Dd + (s & 15) * 16 + j * 4);
        }
        cpcommit();
    }

    int sw = tid & 3;

#pragma unroll 1
    for (int t = 0; t < 2; t++) {
        u64 acc[8];
#pragma unroll
        for (int p = 0; p < 8; p++) acc[p] = 0ull;
        u64 sq = 0ull;

#pragma unroll 1
        for (int s2 = 0; s2 < 16; s2++) {
            int s = t * 16 + s2;
            cpwait2();
            __syncthreads();
            const float* fb = fs + ((s & 3) << 12);
#pragma unroll
            for (int jj = 0; jj < 4; jj++) {
                ulonglong2 f2 = *(const ulonglong2*)&fb[tid * 16 + ((jj ^ sw) << 2)];
                fma2(sq, f2.x, f2.x); fma2(sq, f2.y, f2.y);
#pragma unroll
                for (int p = 0; p < 8; p++) {
                    ulonglong2 q2 = *(const ulonglong2*)(pn_s + p * 64 + s2 * 4 + jj);
                    fma2(acc[p], f2.x, q2.x);
                    fma2(acc[p], f2.y, q2.y);
                }
            }
            int ss = s + 3;
            if (ss < 32) {
#pragma unroll
                for (int k = 0; k < 4; k++) {
                    int lrow = r0 + 64 * k;
                    cpa16(fsb + ((ss & 3) << 14) + lrow * 64 + (j ^ (lrow & 3)) * 16,
                          fbase + (size_t)((ss >> 4) * 256 + lrow) * Dd + (ss & 15) * 16 + j * 4);
                }
            }
            cpcommit();
        }

        int m = c8 * 512 + t * 256 + tid;
        float2 sv = upk(sq);
        float rn = 1.f / fmaxf(sqrtf(sv.x + sv.y), EPSC);
#pragma unroll
        for (int p = 0; p < 8; p++) {
            float2 a = upk(acc[p]);
            out[((size_t)b * Pp + p) * Mm + m] = (a.x + a.y) * rn;
        }
        __syncthreads();
    }
}

extern "C" void kernel_launch(void* const* d_in, const int* in_sizes, int n_in,
                              void* d_out, int out_size) {
    const float* protos = (const float*)d_in[0];
    const float* feats  = (const float*)d_in[1];
    const float* forg   = (const float*)d_in[2];
    float* out = (float*)d_out;

    cudaFuncSetAttribute(k_sim<true, false>,
                         cudaFuncAttributeMaxDynamicSharedMemorySize, SIMSMEM);
    cudaFuncSetAttribute(k_sim<false, true>,
                         cudaFuncAttributeMaxDynamicSharedMemorySize, SIMSMEM);
    cudaFuncSetAttribute(k_simmap,
                         cudaFuncAttributeMaxDynamicSharedMemorySize, SIMSMEM);

    k_norm0<<<BPc, 256>>>(protos);

    k_sim<true, false><<<Bb * 8, 256, SIMSMEM>>>(feats);
    k_stats<false><<<Bb * 16, 256>>>(0);
    k_update<<<Bb * 8, 256>>>(feats, 0);
    k_reduce<<<BPc, 256>>>(out, 1);

    for (int t = 1; t < 5; t++) {
        k_sim<false, true><<<Bb * 8, 256, SIMSMEM>>>(feats);
        k_stats<true><<<Bb * 16, 256>>>((t - 1) & 1);
        k_update<<<Bb * 8, 256>>>(feats, t & 1);
        k_reduce<<<BPc, 256>>>(out, (t + 1) & 1);
    }

    k_simmap<<<Bb * 8, 256, SIMSMEM>>>(forg, out + (size_t)BPc * Dd);
}

// round 15
// speedup vs baseline: 1.1904x; 1.0469x over previous
#include <cuda_runtime.h>
#include <math.h>

#define Bb 64
#define Pp 8
#define Nn 4096
#define Dd 256
#define Mm 4096
#define BPc 512
#define EPSC 1e-8f
#define FULLW 0xFFFFFFFFu

// ---- static device scratch ----
__device__ float    g_sim[(size_t)Bb * Nn * Pp];   // raw sim (never overwritten)
__device__ float    g_rnorm[Bb * Nn];
__device__ float    g_pn[BPc * Dd];
__device__ unsigned g_max[BPc];
__device__ float    g_isv[BPc];
__device__ float    g_zpart[Bb * 16 * Pp];
__device__ int      g_cnt[2][BPc];
__device__ int      g_idx[Bb * Nn];
__device__ float    g_msum[Bb * 16 * Pp];
__device__ float    g_ppart[(size_t)Bb * 16 * Pp * Dd];

typedef unsigned long long u64;

__device__ __forceinline__ void fma2(u64& d, u64 a, u64 b) {
    asm("fma.rn.f32x2 %0, %1, %2, %0;" : "+l"(d) : "l"(a), "l"(b));
}
__device__ __forceinline__ void add2(u64& d, u64 a) {
    asm("add.rn.f32x2 %0, %0, %1;" : "+l"(d) : "l"(a));
}
__device__ __forceinline__ float2 upk(u64 v) {
    float2 r; asm("mov.b64 {%0,%1}, %2;" : "=f"(r.x), "=f"(r.y) : "l"(v)); return r;
}
__device__ __forceinline__ u64 pk(float x, float y) {
    u64 r; asm("mov.b64 %0, {%1,%2};" : "=l"(r) : "f"(x), "f"(y)); return r;
}

// ---- cp.async helpers ----
__device__ __forceinline__ void cpa16(unsigned dst, const void* src) {
    asm volatile("cp.async.cg.shared.global [%0], [%1], 16;" :: "r"(dst), "l"(src));
}
__device__ __forceinline__ void cpcommit() { asm volatile("cp.async.commit_group;"); }
__device__ __forceinline__ void cpwait2() { asm volatile("cp.async.wait_group 2;"); }

__device__ __forceinline__ unsigned f2ord(float f) {
    unsigned u = __float_as_uint(f);
    return (u & 0x80000000u) ? ~u : (u | 0x80000000u);
}
__device__ __forceinline__ float ord2f(unsigned u) {
    return (u & 0x80000000u) ? __uint_as_float(u & 0x7FFFFFFFu) : __uint_as_float(~u);
}

template<bool MX>
__device__ __forceinline__ void red8(float v[8]) {
#pragma unroll
    for (int off = 16; off; off >>= 1) {
#pragma unroll
        for (int p = 0; p < 8; p++) {
            float o = __shfl_xor_sync(FULLW, v[p], off);
            v[p] = MX ? fmaxf(v[p], o) : (v[p] + o);
        }
    }
}

__device__ __forceinline__ float block_sum256(float v, float* r8) {
#pragma unroll
    for (int off = 16; off; off >>= 1) v += __shfl_xor_sync(FULLW, v, off);
    if ((threadIdx.x & 31) == 0) r8[threadIdx.x >> 5] = v;
    __syncthreads();
    if (threadIdx.x == 0) {
        float t = 0.f;
#pragma unroll
        for (int w = 0; w < 8; w++) t += r8[w];
        r8[0] = t;
    }
    __syncthreads();
    return r8[0];
}

// ---- init ----
__global__ void __launch_bounds__(256) k_norm0(const float* __restrict__ pin) {
    __shared__ float r8[8];
    int bp = blockIdx.x, tid = threadIdx.x;
    float v = pin[(size_t)bp * Dd + tid];
    float ss = block_sum256(v * v, r8);
    g_pn[(size_t)bp * Dd + tid] = v / fmaxf(sqrtf(ss), EPSC);
    if (tid == 0) { g_max[bp] = 0u; g_cnt[0][bp] = 0; g_cnt[1][bp] = 0; }
}

// ---- sim pass: 3-stage cp.async ring, 4 CTAs/SM ----
#define SIMSMEM (8192 + 3 * 16384 + 256)

template<bool FIRST, bool DENS>
__global__ void __launch_bounds__(256, 4) k_sim(const float* __restrict__ feats) {
    extern __shared__ char smraw[];
    float4* pn_s = (float4*)smraw;
    float*  fs   = (float*)(smraw + 8192);
    float*  red  = (float*)(smraw + 8192 + 3 * 16384);

    int b = blockIdx.x >> 4, c = blockIdx.x & 15;
    int tid = threadIdx.x, lane = tid & 31, wid = tid >> 5;

    const float4* psrc = (const float4*)g_pn + (size_t)b * 512;
    for (int i = tid; i < 512; i += 256) pn_s[i] = psrc[i];

    const float* fbase = feats + ((size_t)b * Nn + c * 256) * Dd;
    int r0 = tid >> 2, j = tid & 3;
    int jc = j ^ (r0 & 3);
    unsigned fsb = (unsigned)__cvta_generic_to_shared(fs);

#pragma unroll
    for (int s = 0; s < 3; s++) {
#pragma unroll
        for (int k = 0; k < 4; k++) {
            int row = r0 + 64 * k;
            cpa16(fsb + (s << 14) + row * 64 + (j ^ (row & 3)) * 16,
                  fbase + (size_t)row * Dd + s * 16 + j * 4);
        }
        cpcommit();
    }
    (void)jc;

    u64 acc[8];
#pragma unroll
    for (int p = 0; p < 8; p++) acc[p] = 0ull;
    u64 sq = 0ull;
    int sw = tid & 3;

    int buf = 0;
#pragma unroll 1
    for (int s = 0; s < 16; s++) {
        cpwait2();
        __syncthreads();
        const float* fb = fs + (buf << 12);
#pragma unroll
        for (int jj = 0; jj < 4; jj++) {
            ulonglong2 f2 = *(const ulonglong2*)&fb[tid * 16 + ((jj ^ sw) << 2)];
            if (FIRST) { fma2(sq, f2.x, f2.x); fma2(sq, f2.y, f2.y); }
#pragma unroll
            for (int p = 0; p < 8; p++) {
                ulonglong2 q2 = *(const ulonglong2*)(pn_s + p * 64 + s * 4 + jj);
                fma2(acc[p], f2.x, q2.x);
                fma2(acc[p], f2.y, q2.y);
            }
        }
        __syncthreads();
        int ss = s + 3;
        if (ss < 16) {
#pragma unroll
            for (int k = 0; k < 4; k++) {
                int row = r0 + 64 * k;
                cpa16(fsb + (buf << 14) + row * 64 + (j ^ (row & 3)) * 16,
                      fbase + (size_t)row * Dd + ss * 16 + j * 4);
            }
        }
        cpcommit();
        buf = (buf == 2) ? 0 : buf + 1;
    }

    int n = c * 256 + tid;
    float rn;
    if (FIRST) {
        float2 sv = upk(sq);
        rn = 1.f / fmaxf(sqrtf(sv.x + sv.y), EPSC);
        g_rnorm[b * Nn + n] = rn;
    } else rn = g_rnorm[b * Nn + n];

    float sim[8];
#pragma unroll
    for (int p = 0; p < 8; p++) {
        float2 a = upk(acc[p]);
        sim[p] = (a.x + a.y) * rn;
    }
    float4* o = (float4*)(g_sim + ((size_t)b * Nn + n) * 8);
    o[0] = make_float4(sim[0], sim[1], sim[2], sim[3]);
    o[1] = make_float4(sim[4], sim[5], sim[6], sim[7]);

    float mv[8];
#pragma unroll
    for (int p = 0; p < 8; p++) mv[p] = sim[p];
    red8<true>(mv);
    __syncthreads();
    if (lane < 8) red[wid * 8 + lane] = mv[lane];
    __syncthreads();
    if (tid < 8) {
        float m = red[tid];
#pragma unroll
        for (int w = 1; w < 8; w++) m = fmaxf(m, red[w * 8 + tid]);
        atomicMax(&g_max[b * 8 + tid], f2ord(m));
    }

    if (DENS) {
        int a = g_idx[b * Nn + n];
        float dv[8];
#pragma unroll
        for (int p = 0; p < 8; p++) dv[p] = (p == a) ? sim[p] : 0.f;
        red8<false>(dv);
        __syncthreads();
        if (lane < 8) red[wid * 8 + lane] = dv[lane];
        __syncthreads();
        if (tid < 8) {
            float s2 = red[tid];
#pragma unroll
            for (int w = 1; w < 8; w++) s2 += red[w * 8 + tid];
            g_msum[((size_t)b * 16 + c) * 8 + tid] = s2;
        }
    }
}

// ---- stats: tau + Z partials, READ-ONLY on sim ----
template<bool HAS_TAU>
__global__ void __launch_bounds__(256) k_stats(int par) {
    int b = blockIdx.x >> 4, c = blockIdx.x & 15;
    int tid = threadIdx.x, lane = tid & 31, wid = tid >> 5;
    __shared__ float mxs[8], iss[8], red[64];
    if (tid < 8) {
        mxs[tid] = ord2f(g_max[b * 8 + tid]);
        float is;
        if (HAS_TAU) {
            float s = 0.f;
#pragma unroll
            for (int cc = 0; cc < 16; cc++) s += g_msum[((size_t)b * 16 + cc) * 8 + tid];
            int cnt = g_cnt[par][b * 8 + tid];
            float mean = s / (float)(cnt >= 1 ? cnt : 1);
            float dens = (cnt >= 1) ? (1.f - mean) : 1.f;
            is = 1.f / (0.1f * fmaxf(dens, 1e-10f));
        } else {
            is = 100.f;
        }
        iss[tid] = is;
        if (c == 0) g_isv[b * 8 + tid] = is;
    }
    __syncthreads();
    float z[8];
    {
        int n = c * 256 + tid;
        const float4* p4 = (const float4*)(g_sim + ((size_t)b * Nn + n) * 8);
        float4 a = p4[0], cc = p4[1];
        z[0] = expf((a.x  - mxs[0]) * iss[0]);
        z[1] = expf((a.y  - mxs[1]) * iss[1]);
        z[2] = expf((a.z  - mxs[2]) * iss[2]);
        z[3] = expf((a.w  - mxs[3]) * iss[3]);
        z[4] = expf((cc.x - mxs[4]) * iss[4]);
        z[5] = expf((cc.y - mxs[5]) * iss[5]);
        z[6] = expf((cc.z - mxs[6]) * iss[6]);
        z[7] = expf((cc.w - mxs[7]) * iss[7]);
    }
    red8<false>(z);
    if (lane < 8) red[wid * 8 + lane] = z[lane];
    __syncthreads();
    if (tid < 8) {
        float s = red[tid];
#pragma unroll
        for (int w = 1; w < 8; w++) s += red[w * 8 + tid];
        g_zpart[((size_t)b * 16 + c) * 8 + tid] = s;
    }
}

// ---- update v4: raw sim + inline softmax, 2 cols/thread, batched LDG.64 ----
__global__ void __launch_bounds__(256) k_update(const float* __restrict__ feats,
                                                int parw) {
    int b = blockIdx.x >> 4, ch = blockIdx.x & 15;
    int tid = threadIdx.x, lane = tid & 31;
    __shared__ float ws[256];
    __shared__ int   bis[256];
    __shared__ u64   part[8][128];
    __shared__ float mxs[8], iss[8], izs[8];

    if (tid < 8) {
        mxs[tid] = ord2f(g_max[b * 8 + tid]);
        iss[tid] = g_isv[b * 8 + tid];
        float z = 0.f;
#pragma unroll
        for (int q = 0; q < 16; q++) z += g_zpart[((size_t)b * 16 + q) * 8 + tid];
        izs[tid] = 1.f / z;
    }
    __syncthreads();

    int base = ch * 256;
    {
        const float4* sp = (const float4*)(g_sim + ((size_t)b * Nn + base + tid) * 8);
        float4 e0 = sp[0], e1 = sp[1];
        float w[8];
        w[0] = expf((e0.x - mxs[0]) * iss[0]) * izs[0];
        w[1] = expf((e0.y - mxs[1]) * iss[1]) * izs[1];
        w[2] = expf((e0.z - mxs[2]) * iss[2]) * izs[2];
        w[3] = expf((e0.w - mxs[3]) * iss[3]) * izs[3];
        w[4] = expf((e1.x - mxs[4]) * iss[4]) * izs[4];
        w[5] = expf((e1.y - mxs[5]) * iss[5]) * izs[5];
        w[6] = expf((e1.z - mxs[6]) * iss[6]) * izs[6];
        w[7] = expf((e1.w - mxs[7]) * iss[7]) * izs[7];
        int bi = 0; float bw = w[0];
#pragma unroll
        for (int p = 1; p < 8; p++) if (w[p] > bw) { bw = w[p]; bi = p; }
        g_idx[b * Nn + base + tid] = bi;
        ws[tid] = bw;
        bis[tid] = bi;
        int mycnt = 0;
#pragma unroll
        for (int p = 0; p < 8; p++) {
            unsigned mk = __ballot_sync(FULLW, bi == p);
            if (lane == p) mycnt += __popc(mk);
        }
        if (lane < 8) atomicAdd(&g_cnt[parw][b * 8 + lane], mycnt);
    }
    __syncthreads();

    int g2 = tid >> 7;
    int t = tid & 127;
    const float* fb = feats + ((size_t)b * Nn + base + g2 * 128) * Dd;

    u64 acc[8];
#pragma unroll
    for (int p = 0; p < 8; p++) acc[p] = 0ull;

    for (int r0 = 0; r0 < 128; r0 += 8) {
        u64 f[8];
#pragma unroll
        for (int k = 0; k < 8; k++)
            f[k] = __ldg((const u64*)(fb + (size_t)(r0 + k) * Dd + 2 * t));
#pragma unroll
        for (int k = 0; k < 8; k++) {
            int row = (g2 << 7) + r0 + k;
            float wv = ws[row];
            int bi = bis[row];           // uniform across the warp
            u64 wp = pk(wv, wv);
            if (bi < 4) {
                if (bi < 2) { if (bi == 0) fma2(acc[0], wp, f[k]); else fma2(acc[1], wp, f[k]); }
                else        { if (bi == 2) fma2(acc[2], wp, f[k]); else fma2(acc[3], wp, f[k]); }
            } else {
                if (bi < 6) { if (bi == 4) fma2(acc[4], wp, f[k]); else fma2(acc[5], wp, f[k]); }
                else        { if (bi == 6) fma2(acc[6], wp, f[k]); else fma2(acc[7], wp, f[k]); }
            }
        }
    }

    if (g2 == 1) {
#pragma unroll
        for (int p = 0; p < 8; p++) part[p][t] = acc[p];
    }
    __syncthreads();
    if (g2 == 0) {
        float* op = g_ppart + ((size_t)(b * 16 + ch)) * 2048;
#pragma unroll
        for (int p = 0; p < 8; p++) {
            add2(acc[p], part[p][t]);
            float2 a = upk(acc[p]);
            *(float2*)(op + p * 256 + 2 * t) = a;
        }
    }
}

// ---- reduce 16 partials -> prototypes; normalize; reset state ----
__global__ void __launch_bounds__(256) k_reduce(float* __restrict__ outp, int parzero) {
    __shared__ float r8[8];
    int bp = blockIdx.x, b = bp >> 3, p = bp & 7;
    int tid = threadIdx.x;
    float v = 0.f;
#pragma unroll
    for (int c = 0; c < 16; c++)
        v += g_ppart[((size_t)(b * 16 + c)) * 2048 + p * 256 + tid];
    float ss = block_sum256(v * v, r8);
    float rn = 1.f / fmaxf(sqrtf(ss), EPSC);
    outp[(size_t)bp * Dd + tid] = v;
    g_pn[(size_t)bp * Dd + tid] = v * rn;
    if (tid == 0) { g_max[bp] = 0u; g_cnt[parzero][bp] = 0; }
}

// ---- final sim_map: 3-stage ring, inline rnorm ----
__global__ void __launch_bounds__(256, 4) k_simmap(const float* __restrict__ forg,
                                                   float* __restrict__ out) {
    extern __shared__ char smraw[];
    float4* pn_s = (float4*)smraw;
    float*  fs   = (float*)(smraw + 8192);

    int b = blockIdx.x >> 4, c = blockIdx.x & 15;
    int tid = threadIdx.x;

    const float4* psrc = (const float4*)g_pn + (size_t)b * 512;
    for (int i = tid; i < 512; i += 256) pn_s[i] = psrc[i];

    const float* fbase = forg + (size_t)c * 256 * Dd;
    int r0 = tid >> 2, j = tid & 3;
    unsigned fsb = (unsigned)__cvta_generic_to_shared(fs);

#pragma unroll
    for (int s = 0; s < 3; s++) {
#pragma unroll
        for (int k = 0; k < 4; k++) {
            int row = r0 + 64 * k;
            cpa16(fsb + (s << 14) + row * 64 + (j ^ (row & 3)) * 16,
                  fbase + (size_t)row * Dd + s * 16 + j * 4);
        }
        cpcommit();
    }

    u64 acc[8];
#pragma unroll
    for (int p = 0; p < 8; p++) acc[p] = 0ull;
    u64 sq = 0ull;
    int sw = tid & 3;

    int buf = 0;
#pragma unroll 1
    for (int s = 0; s < 16; s++) {
        cpwait2();
        __syncthreads();
        const float* fb = fs + (buf << 12);
#pragma unroll
        for (int jj = 0; jj < 4; jj++) {
            ulonglong2 f2 = *(const ulonglong2*)&fb[tid * 16 + ((jj ^ sw) << 2)];
            fma2(sq, f2.x, f2.x); fma2(sq, f2.y, f2.y);
#pragma unroll
            for (int p = 0; p < 8; p++) {
                ulonglong2 q2 = *(const ulonglong2*)(pn_s + p * 64 + s * 4 + jj);
                fma2(acc[p], f2.x, q2.x);
                fma2(acc[p], f2.y, q2.y);
            }
        }
        __syncthreads();
        int ss = s + 3;
        if (ss < 16) {
#pragma unroll
            for (int k = 0; k < 4; k++) {
                int row = r0 + 64 * k;
                cpa16(fsb + (buf << 14) + row * 64 + (j ^ (row & 3)) * 16,
                      fbase + (size_t)row * Dd + ss * 16 + j * 4);
            }
        }
        cpcommit();
        buf = (buf == 2) ? 0 : buf + 1;
    }

    int m = c * 256 + tid;
    float2 sv = upk(sq);
    float rn = 1.f / fmaxf(sqrtf(sv.x + sv.y), EPSC);
#pragma unroll
    for (int p = 0; p < 8; p++) {
        float2 a = upk(acc[p]);
        out[((size_t)b * Pp + p) * Mm + m] = (a.x + a.y) * rn;
    }
}

extern "C" void kernel_launch(void* const* d_in, const int* in_sizes, int n_in,
                              void* d_out, int out_size) {
    const float* protos = (const float*)d_in[0];
    const float* feats  = (const float*)d_in[1];
    const float* forg   = (const float*)d_in[2];
    float* out = (float*)d_out;

    cudaFuncSetAttribute(k_sim<true, false>,
                         cudaFuncAttributeMaxDynamicSharedMemorySize, SIMSMEM);
    cudaFuncSetAttribute(k_sim<false, true>,
                         cudaFuncAttributeMaxDynamicSharedMemorySize, SIMSMEM);
    cudaFuncSetAttribute(k_simmap,
                         cudaFuncAttributeMaxDynamicSharedMemorySize, SIMSMEM);

    k_norm0<<<BPc, 256>>>(protos);

    k_sim<true, false><<<Bb * 16, 256, SIMSMEM>>>(feats);
    k_stats<false><<<Bb * 16, 256>>>(0);
    k_update<<<Bb * 16, 256>>>(feats, 0);
    k_reduce<<<BPc, 256>>>(out, 1);

    for (int t = 1; t < 5; t++) {
        k_sim<false, true><<<Bb * 16, 256, SIMSMEM>>>(feats);
        k_stats<true><<<Bb * 16, 256>>>((t - 1) & 1);
        k_update<<<Bb * 16, 256>>>(feats, t & 1);
        k_reduce<<<BPc, 256>>>(out, (t + 1) & 1);
    }

    k_simmap<<<Bb * 16, 256, SIMSMEM>>>(forg, out + (size_t)BPc * Dd);
}

// round 16
// speedup vs baseline: 1.2009x; 1.0088x over previous
#include <cuda_runtime.h>
#include <math.h>

#define Bb 64
#define Pp 8
#define Nn 4096
#define Dd 256
#define Mm 4096
#define BPc 512
#define EPSC 1e-8f
#define FULLW 0xFFFFFFFFu

// ---- static device scratch ----
__device__ float    g_sim[(size_t)Bb * Nn * Pp];   // raw sim, exp'd in place by k_stats
__device__ float    g_rnorm[Bb * Nn];
__device__ float    g_pn[BPc * Dd];
__device__ unsigned g_max[BPc];
__device__ float    g_zpart[Bb * 16 * Pp];
__device__ int      g_cnt[2][BPc];
__device__ int      g_idx[Bb * Nn];
__device__ float    g_msum[Bb * 16 * Pp];
__device__ float    g_ppart[(size_t)Bb * 16 * Pp * Dd];

typedef unsigned long long u64;

__device__ __forceinline__ void fma2(u64& d, u64 a, u64 b) {
    asm("fma.rn.f32x2 %0, %1, %2, %0;" : "+l"(d) : "l"(a), "l"(b));
}
__device__ __forceinline__ void add2(u64& d, u64 a) {
    asm("add.rn.f32x2 %0, %0, %1;" : "+l"(d) : "l"(a));
}
__device__ __forceinline__ float2 upk(u64 v) {
    float2 r; asm("mov.b64 {%0,%1}, %2;" : "=f"(r.x), "=f"(r.y) : "l"(v)); return r;
}
__device__ __forceinline__ u64 pk(float x, float y) {
    u64 r; asm("mov.b64 %0, {%1,%2};" : "=l"(r) : "f"(x), "f"(y)); return r;
}

// ---- cp.async helpers ----
__device__ __forceinline__ void cpa16(unsigned dst, const void* src) {
    asm volatile("cp.async.cg.shared.global [%0], [%1], 16;" :: "r"(dst), "l"(src));
}
__device__ __forceinline__ void cpcommit() { asm volatile("cp.async.commit_group;"); }
__device__ __forceinline__ void cpwait0() { asm volatile("cp.async.wait_group 0;"); }

__device__ __forceinline__ unsigned f2ord(float f) {
    unsigned u = __float_as_uint(f);
    return (u & 0x80000000u) ? ~u : (u | 0x80000000u);
}
__device__ __forceinline__ float ord2f(unsigned u) {
    return (u & 0x80000000u) ? __uint_as_float(u & 0x7FFFFFFFu) : __uint_as_float(~u);
}

template<bool MX>
__device__ __forceinline__ void red8(float v[8]) {
#pragma unroll
    for (int off = 16; off; off >>= 1) {
#pragma unroll
        for (int p = 0; p < 8; p++) {
            float o = __shfl_xor_sync(FULLW, v[p], off);
            v[p] = MX ? fmaxf(v[p], o) : (v[p] + o);
        }
    }
}

__device__ __forceinline__ float block_sum256(float v, float* r8) {
#pragma unroll
    for (int off = 16; off; off >>= 1) v += __shfl_xor_sync(FULLW, v, off);
    if ((threadIdx.x & 31) == 0) r8[threadIdx.x >> 5] = v;
    __syncthreads();
    if (threadIdx.x == 0) {
        float t = 0.f;
#pragma unroll
        for (int w = 0; w < 8; w++) t += r8[w];
        r8[0] = t;
    }
    __syncthreads();
    return r8[0];
}

// ---- init ----
__global__ void __launch_bounds__(256) k_norm0(const float* __restrict__ pin) {
    __shared__ float r8[8];
    int bp = blockIdx.x, tid = threadIdx.x;
    float v = pin[(size_t)bp * Dd + tid];
    float ss = block_sum256(v * v, r8);
    g_pn[(size_t)bp * Dd + tid] = v / fmaxf(sqrtf(ss), EPSC);
    if (tid == 0) { g_max[bp] = 0u; g_cnt[0][bp] = 0; g_cnt[1][bp] = 0; }
}

// ---- sim pass: 2-stage cp.async ring, 5 CTAs/SM ----
// dyn smem: pn_s 8192 | fs 2*16384 = 40960 B; red overlays fs after main loop
#define SIMSMEM (8192 + 2 * 16384)

template<bool FIRST, bool DENS>
__global__ void __launch_bounds__(256, 5) k_sim(const float* __restrict__ feats) {
    extern __shared__ char smraw[];
    float4* pn_s = (float4*)smraw;
    float*  fs   = (float*)(smraw + 8192);
    float*  red  = (float*)(smraw + 8192);   // overlay (used only after main loop)

    int b = blockIdx.x >> 4, c = blockIdx.x & 15;
    int tid = threadIdx.x, lane = tid & 31, wid = tid >> 5;

    const float4* psrc = (const float4*)g_pn + (size_t)b * 512;
    for (int i = tid; i < 512; i += 256) pn_s[i] = psrc[i];

    const float* fbase = feats + ((size_t)b * Nn + c * 256) * Dd;
    int r0 = tid >> 2, j = tid & 3;
    unsigned fsb = (unsigned)__cvta_generic_to_shared(fs);

    // prologue: stage 0
#pragma unroll
    for (int k = 0; k < 4; k++) {
        int row = r0 + 64 * k;
        cpa16(fsb + row * 64 + (j ^ (row & 3)) * 16,
              fbase + (size_t)row * Dd + j * 4);
    }
    cpcommit();

    u64 acc[8];
#pragma unroll
    for (int p = 0; p < 8; p++) acc[p] = 0ull;
    u64 sq = 0ull;
    int sw = tid & 3;

#pragma unroll 1
    for (int s = 0; s < 16; s++) {
        cpwait0();
        __syncthreads();
        if (s + 1 < 16) {
            int nb = (s + 1) & 1;
#pragma unroll
            for (int k = 0; k < 4; k++) {
                int row = r0 + 64 * k;
                cpa16(fsb + (nb << 14) + row * 64 + (j ^ (row & 3)) * 16,
                      fbase + (size_t)row * Dd + (s + 1) * 16 + j * 4);
            }
            cpcommit();
        }
        const float* fb = fs + ((s & 1) << 12);
#pragma unroll
        for (int jj = 0; jj < 4; jj++) {
            ulonglong2 f2 = *(const ulonglong2*)&fb[tid * 16 + ((jj ^ sw) << 2)];
            if (FIRST) { fma2(sq, f2.x, f2.x); fma2(sq, f2.y, f2.y); }
#pragma unroll
            for (int p = 0; p < 8; p++) {
                ulonglong2 q2 = *(const ulonglong2*)(pn_s + p * 64 + s * 4 + jj);
                fma2(acc[p], f2.x, q2.x);
                fma2(acc[p], f2.y, q2.y);
            }
        }
    }

    int n = c * 256 + tid;
    float rn;
    if (FIRST) {
        float2 sv = upk(sq);
        rn = 1.f / fmaxf(sqrtf(sv.x + sv.y), EPSC);
        g_rnorm[b * Nn + n] = rn;
    } else rn = g_rnorm[b * Nn + n];

    float sim[8];
#pragma unroll
    for (int p = 0; p < 8; p++) {
        float2 a = upk(acc[p]);
        sim[p] = (a.x + a.y) * rn;
    }
    float4* o = (float4*)(g_sim + ((size_t)b * Nn + n) * 8);
    o[0] = make_float4(sim[0], sim[1], sim[2], sim[3]);
    o[1] = make_float4(sim[4], sim[5], sim[6], sim[7]);

    float mv[8];
#pragma unroll
    for (int p = 0; p < 8; p++) mv[p] = sim[p];
    red8<true>(mv);
    __syncthreads();
    if (lane < 8) red[wid * 8 + lane] = mv[lane];
    __syncthreads();
    if (tid < 8) {
        float m = red[tid];
#pragma unroll
        for (int w = 1; w < 8; w++) m = fmaxf(m, red[w * 8 + tid]);
        atomicMax(&g_max[b * 8 + tid], f2ord(m));
    }

    if (DENS) {
        int a = g_idx[b * Nn + n];
        float dv[8];
#pragma unroll
        for (int p = 0; p < 8; p++) dv[p] = (p == a) ? sim[p] : 0.f;
        red8<false>(dv);
        __syncthreads();
        if (lane < 8) red[wid * 8 + lane] = dv[lane];
        __syncthreads();
        if (tid < 8) {
            float s2 = red[tid];
#pragma unroll
            for (int w = 1; w < 8; w++) s2 += red[w * 8 + tid];
            g_msum[((size_t)b * 16 + c) * 8 + tid] = s2;
        }
    }
}

// ---- stats (R10): tau; exp in place; Z partials ----
template<bool HAS_TAU>
__global__ void __launch_bounds__(256) k_stats(int par) {
    int b = blockIdx.x >> 4, c = blockIdx.x & 15;
    int tid = threadIdx.x, lane = tid & 31, wid = tid >> 5;
    __shared__ float mxs[8], iss[8], red[64];
    if (tid < 8) {
        mxs[tid] = ord2f(g_max[b * 8 + tid]);
        float is;
        if (HAS_TAU) {
            float s = 0.f;
#pragma unroll
            for (int cc = 0; cc < 16; cc++) s += g_msum[((size_t)b * 16 + cc) * 8 + tid];
            int cnt = g_cnt[par][b * 8 + tid];
            float mean = s / (float)(cnt >= 1 ? cnt : 1);
            float dens = (cnt >= 1) ? (1.f - mean) : 1.f;
            is = 1.f / (0.1f * fmaxf(dens, 1e-10f));
        } else {
            is = 100.f;
        }
        iss[tid] = is;
    }
    __syncthreads();
    float z[8];
    {
        int n = c * 256 + tid;
        float4* p4 = (float4*)(g_sim + ((size_t)b * Nn + n) * 8);
        float4 a = p4[0], cc = p4[1];
        a.x  = expf((a.x  - mxs[0]) * iss[0]); z[0] = a.x;
        a.y  = expf((a.y  - mxs[1]) * iss[1]); z[1] = a.y;
        a.z  = expf((a.z  - mxs[2]) * iss[2]); z[2] = a.z;
        a.w  = expf((a.w  - mxs[3]) * iss[3]); z[3] = a.w;
        cc.x = expf((cc.x - mxs[4]) * iss[4]); z[4] = cc.x;
        cc.y = expf((cc.y - mxs[5]) * iss[5]); z[5] = cc.y;
        cc.z = expf((cc.z - mxs[6]) * iss[6]); z[6] = cc.z;
        cc.w = expf((cc.w - mxs[7]) * iss[7]); z[7] = cc.w;
        p4[0] = a; p4[1] = cc;
    }
    red8<false>(z);
    if (lane < 8) red[wid * 8 + lane] = z[lane];
    __syncthreads();
    if (tid < 8) {
        float s = red[tid];
#pragma unroll
        for (int w = 1; w < 8; w++) s += red[w * 8 + tid];
        g_zpart[((size_t)b * 16 + c) * 8 + tid] = s;
    }
}

// ---- update v4 (R10): exp'd sim, 2 cols/thread, batched LDG.64 ----
__global__ void __launch_bounds__(256) k_update(const float* __restrict__ feats,
                                                int parw) {
    int b = blockIdx.x >> 4, ch = blockIdx.x & 15;
    int tid = threadIdx.x, lane = tid & 31;
    __shared__ float ws[256];
    __shared__ int   bis[256];
    __shared__ u64   part[8][128];
    __shared__ float izs[8];

    if (tid < 8) {
        float z = 0.f;
#pragma unroll
        for (int q = 0; q < 16; q++) z += g_zpart[((size_t)b * 16 + q) * 8 + tid];
        izs[tid] = 1.f / z;
    }
    __syncthreads();

    int base = ch * 256;
    {
        const float4* sp = (const float4*)(g_sim + ((size_t)b * Nn + base + tid) * 8);
        float4 e0 = sp[0], e1 = sp[1];
        float w[8] = { e0.x * izs[0], e0.y * izs[1], e0.z * izs[2], e0.w * izs[3],
                       e1.x * izs[4], e1.y * izs[5], e1.z * izs[6], e1.w * izs[7] };
        int bi = 0; float bw = w[0];
#pragma unroll
        for (int p = 1; p < 8; p++) if (w[p] > bw) { bw = w[p]; bi = p; }
        g_idx[b * Nn + base + tid] = bi;
        ws[tid] = bw;
        bis[tid] = bi;
        int mycnt = 0;
#pragma unroll
        for (int p = 0; p < 8; p++) {
            unsigned mk = __ballot_sync(FULLW, bi == p);
            if (lane == p) mycnt += __popc(mk);
        }
        if (lane < 8) atomicAdd(&g_cnt[parw][b * 8 + lane], mycnt);
    }
    __syncthreads();

    int g2 = tid >> 7;
    int t = tid & 127;
    const float* fb = feats + ((size_t)b * Nn + base + g2 * 128) * Dd;

    u64 acc[8];
#pragma unroll
    for (int p = 0; p < 8; p++) acc[p] = 0ull;

    for (int r0 = 0; r0 < 128; r0 += 8) {
        u64 f[8];
#pragma unroll
        for (int k = 0; k < 8; k++)
            f[k] = __ldg((const u64*)(fb + (size_t)(r0 + k) * Dd + 2 * t));
#pragma unroll
        for (int k = 0; k < 8; k++) {
            int row = (g2 << 7) + r0 + k;
            float wv = ws[row];
            int bi = bis[row];           // uniform across the warp
            u64 wp = pk(wv, wv);
            if (bi < 4) {
                if (bi < 2) { if (bi == 0) fma2(acc[0], wp, f[k]); else fma2(acc[1], wp, f[k]); }
                else        { if (bi == 2) fma2(acc[2], wp, f[k]); else fma2(acc[3], wp, f[k]); }
            } else {
                if (bi < 6) { if (bi == 4) fma2(acc[4], wp, f[k]); else fma2(acc[5], wp, f[k]); }
                else        { if (bi == 6) fma2(acc[6], wp, f[k]); else fma2(acc[7], wp, f[k]); }
            }
        }
    }

    if (g2 == 1) {
#pragma unroll
        for (int p = 0; p < 8; p++) part[p][t] = acc[p];
    }
    __syncthreads();
    if (g2 == 0) {
        float* op = g_ppart + ((size_t)(b * 16 + ch)) * 2048;
#pragma unroll
        for (int p = 0; p < 8; p++) {
            add2(acc[p], part[p][t]);
            float2 a = upk(acc[p]);
            *(float2*)(op + p * 256 + 2 * t) = a;
        }
    }
}

// ---- reduce 16 partials -> prototypes; normalize; reset state ----
__global__ void __launch_bounds__(256) k_reduce(float* __restrict__ outp, int parzero) {
    __shared__ float r8[8];
    int bp = blockIdx.x, b = bp >> 3, p = bp & 7;
    int tid = threadIdx.x;
    float v = 0.f;
#pragma unroll
    for (int c = 0; c < 16; c++)
        v += g_ppart[((size_t)(b * 16 + c)) * 2048 + p * 256 + tid];
    float ss = block_sum256(v * v, r8);
    float rn = 1.f / fmaxf(sqrtf(ss), EPSC);
    outp[(size_t)bp * Dd + tid] = v;
    g_pn[(size_t)bp * Dd + tid] = v * rn;
    if (tid == 0) { g_max[bp] = 0u; g_cnt[parzero][bp] = 0; }
}

// ---- final sim_map: 2-stage ring, inline rnorm ----
__global__ void __launch_bounds__(256, 5) k_simmap(const float* __restrict__ forg,
                                                   float* __restrict__ out) {
    extern __shared__ char smraw[];
    float4* pn_s = (float4*)smraw;
    float*  fs   = (float*)(smraw + 8192);

    int b = blockIdx.x >> 4, c = blockIdx.x & 15;
    int tid = threadIdx.x;

    const float4* psrc = (const float4*)g_pn + (size_t)b * 512;
    for (int i = tid; i < 512; i += 256) pn_s[i] = psrc[i];

    const float* fbase = forg + (size_t)c * 256 * Dd;
    int r0 = tid >> 2, j = tid & 3;
    unsigned fsb = (unsigned)__cvta_generic_to_shared(fs);

#pragma unroll
    for (int k = 0; k < 4; k++) {
        int row = r0 + 64 * k;
        cpa16(fsb + row * 64 + (j ^ (row & 3)) * 16,
              fbase + (size_t)row * Dd + j * 4);
    }
    cpcommit();

    u64 acc[8];
#pragma unroll
    for (int p = 0; p < 8; p++) acc[p] = 0ull;
    u64 sq = 0ull;
    int sw = tid & 3;

#pragma unroll 1
    for (int s = 0; s < 16; s++) {
        cpwait0();
        __syncthreads();
        if (s + 1 < 16) {
            int nb = (s + 1) & 1;
#pragma unroll
            for (int k = 0; k < 4; k++) {
                int row = r0 + 64 * k;
                cpa16(fsb + (nb << 14) + row * 64 + (j ^ (row & 3)) * 16,
                      fbase + (size_t)row * Dd + (s + 1) * 16 + j * 4);
            }
            cpcommit();
        }
        const float* fb = fs + ((s & 1) << 12);
#pragma unroll
        for (int jj = 0; jj < 4; jj++) {
            ulonglong2 f2 = *(const ulonglong2*)&fb[tid * 16 + ((jj ^ sw) << 2)];
            fma2(sq, f2.x, f2.x); fma2(sq, f2.y, f2.y);
#pragma unroll
            for (int p = 0; p < 8; p++) {
                ulonglong2 q2 = *(const ulonglong2*)(pn_s + p * 64 + s * 4 + jj);
                fma2(acc[p], f2.x, q2.x);
                fma2(acc[p], f2.y, q2.y);
            }
        }
    }

    int m = c * 256 + tid;
    float2 sv = upk(sq);
    float rn = 1.f / fmaxf(sqrtf(sv.x + sv.y), EPSC);
#pragma unroll
    for (int p = 0; p < 8; p++) {
        float2 a = upk(acc[p]);
        out[((size_t)b * Pp + p) * Mm + m] = (a.x + a.y) * rn;
    }
}

extern "C" void kernel_launch(void* const* d_in, const int* in_sizes, int n_in,
                              void* d_out, int out_size) {
    const float* protos = (const float*)d_in[0];
    const float* feats  = (const float*)d_in[1];
    const float* forg   = (const float*)d_in[2];
    float* out = (float*)d_out;

    cudaFuncSetAttribute(k_sim<true, false>,
                         cudaFuncAttributeMaxDynamicSharedMemorySize, SIMSMEM);
    cudaFuncSetAttribute(k_sim<false, true>,
                         cudaFuncAttributeMaxDynamicSharedMemorySize, SIMSMEM);
    cudaFuncSetAttribute(k_simmap,
                         cudaFuncAttributeMaxDynamicSharedMemorySize, SIMSMEM);

    k_norm0<<<BPc, 256>>>(protos);

    k_sim<true, false><<<Bb * 16, 256, SIMSMEM>>>(feats);
    k_stats<false><<<Bb * 16, 256>>>(0);
    k_update<<<Bb * 16, 256>>>(feats, 0);
    k_reduce<<<BPc, 256>>>(out, 1);

    for (int t = 1; t < 5; t++) {
        k_sim<false, true><<<Bb * 16, 256, SIMSMEM>>>(feats);
        k_stats<true><<<Bb * 16, 256>>>((t - 1) & 1);
        k_update<<<Bb * 16, 256>>>(feats, t & 1);
        k_reduce<<<BPc, 256>>>(out, (t + 1) & 1);
    }

    k_simmap<<<Bb * 16, 256, SIMSMEM>>>(forg, out + (size_t)BPc * Dd);
}